// round 8
// baseline (speedup 1.0000x reference)
#include <cuda_runtime.h>
#include <cuda_bf16.h>

// Upscale_15358803050749: upfirdn2d up=2, 4x4 kernel [1,3,3,1]^2, gain 4.
// x: (8,128,128,128) f32 -> out: (8,128,256,256) f32.
//
// Polyphase (reference's dilated conv, pad0=2), separably factored:
//   K[v][u] = C[v]*D[u],  D[u]=K[0][u],  C[v]=K[v][0]/K[0][0]  (C0==1)
//
// R8 = R7 (wrapped-vector halos, no scalar loads, no shfl) with:
//  - vertical-FIRST combine (4 rows -> 4 out-row vectors over the 6 shared
//    source values, masks applied after; fewer FMAs, fewer live regs)
//  - 128-thread blocks + __launch_bounds__(128,10) for ~62% occupancy
//
// Load layout per thread (2 input rows -> 4 output rows x 8 cols):
//   V @ ix0, U @ (ix0+4)&127 for rows iy0-1..iy0+2 (8 independent LDG.128).
//   Lane 31's U wraps to col 0; its outputs wrap to out cols [0..3], needing
//   exactly two masked terms per out row (V.w-term, U.x-term in H[3]/H[4]).

#define W_IN   128
#define H_IN   128
#define W_OUT  256
#define NC     1024          // 8 * 128 planes
#define DRP    64            // thread-rows per plane (2 input rows each)

__global__ __launch_bounds__(128, 10)
void Upscale_15358803050749_kernel(const float* __restrict__ x,
                                   const float* __restrict__ k,
                                   float* __restrict__ out) {
    int t    = blockIdx.x * blockDim.x + threadIdx.x;
    int lane = t & 31;
    int rp   = t >> 5;
    int ry   = rp & (DRP - 1);
    int pl   = rp >> 6;                   // plane 0..NC-1
    int iy0  = ry * 2;                    // first input row of this thread
    int ix0  = lane * 4;
    int ixu  = (ix0 + 4) & (W_IN - 1);    // wrapped halo-vector column

    const float* xp = x   + pl * (H_IN * W_IN);
    float*       op = out + pl * (256 * W_OUT);

    // ---- 8 independent vector loads (MLP=8), no scalar loads ----
    bool vm = (iy0 > 0);
    bool vc = (iy0 + 2 < H_IN);
    const float* rm_p = xp + (vm ? (iy0 - 1) * W_IN : 0);
    const float* ra_p = xp + iy0 * W_IN;
    const float* rb_p = xp + (iy0 + 1) * W_IN;
    const float* rc_p = xp + (vc ? (iy0 + 2) * W_IN : 0);

    float4 Vm = *reinterpret_cast<const float4*>(rm_p + ix0);
    float4 Um = *reinterpret_cast<const float4*>(rm_p + ixu);
    float4 Va = *reinterpret_cast<const float4*>(ra_p + ix0);
    float4 Ua = *reinterpret_cast<const float4*>(ra_p + ixu);
    float4 Vb = *reinterpret_cast<const float4*>(rb_p + ix0);
    float4 Ub = *reinterpret_cast<const float4*>(rb_p + ixu);
    float4 Vc = *reinterpret_cast<const float4*>(rc_p + ix0);
    float4 Uc = *reinterpret_cast<const float4*>(rc_p + ixu);

    // ---- separable factors ----
    float D0 = __ldg(k + 0), D1 = __ldg(k + 1), D2 = __ldg(k + 2), D3 = __ldg(k + 3);
    float inv = 1.0f / D0;
    float C1 = __ldg(k + 4)  * inv;
    float C2 = __ldg(k + 8)  * inv;
    float C3 = __ldg(k + 12) * inv;     // C0 == 1

    float zm = vm ? 1.f : 0.f;           // row-validity as multiplicative mask
    float zc = vc ? 1.f : 0.f;

    // 6 shared source values per row: V.y V.z V.w U.x U.y U.z
    float m6[6] = { Vm.y*zm, Vm.z*zm, Vm.w*zm, Um.x*zm, Um.y*zm, Um.z*zm };
    float a6[6] = { Va.y, Va.z, Va.w, Ua.x, Ua.y, Ua.z };
    float b6[6] = { Vb.y, Vb.z, Vb.w, Ub.x, Ub.y, Ub.z };
    float c6[6] = { Vc.y*zc, Vc.z*zc, Vc.w*zc, Uc.x*zc, Uc.y*zc, Uc.z*zc };

    // ---- vertical combine FIRST (masks commute: per-lane, row-independent)
    float E0[6], O1[6], E2[6], O3[6];
    #pragma unroll
    for (int j = 0; j < 6; j++) {
        E0[j] = C3 * m6[j] + C1 * a6[j];  // out row 2*iy0
        O1[j] = C2 * a6[j] + b6[j];       // out row 2*iy0+1 (C0=1)
        E2[j] = C3 * a6[j] + C1 * b6[j];  // out row 2*iy0+2
        O3[j] = C2 * b6[j] + c6[j];       // out row 2*iy0+3
    }

    bool last = (lane == 31);             // wrap lane: mask x[128] terms

    // ---- horizontal transform per output row: T[6] -> 8 outputs ----
    // T: [0]=x[4l+1] [1]=x[4l+2] [2]=x[4l+3] [3]=x[4l+4] [4]=x[4l+5] [5]=x[4l+6]
    float o0[8], o1[8], o2[8], o3[8];
    #define HOUT(o, T)                                                    \
    {                                                                     \
        float w2z = last ? 0.f : (T)[2];                                  \
        float x3z = last ? 0.f : (T)[3];                                  \
        o[0] = D3*(T)[0] + D1*(T)[1];                                     \
        o[1] = D2*(T)[1] + D0*(T)[2];                                     \
        o[2] = D3*(T)[1] + D1*(T)[2];                                     \
        o[3] = D2*(T)[2] + D0*x3z;                                        \
        o[4] = D3*w2z    + D1*(T)[3];                                     \
        o[5] = D2*(T)[3] + D0*(T)[4];                                     \
        o[6] = D3*(T)[3] + D1*(T)[4];                                     \
        o[7] = D2*(T)[4] + D0*(T)[5];                                     \
    }
    HOUT(o0, E0)
    HOUT(o1, O1)
    HOUT(o2, E2)
    HOUT(o3, O3)
    #undef HOUT

    // ---- stores: two aligned float4 per row; second wraps for lane 31 ----
    int cA = 8 * lane + 4;                 // cols [8l+4..8l+7]
    int cB = (8 * lane + 8) & (W_OUT - 1); // cols [8l+8..8l+11] (lane31 -> 0..3)
    float* q0 = op + (2 * iy0) * W_OUT;
    float* q1 = q0 + W_OUT;
    float* q2 = q1 + W_OUT;
    float* q3 = q2 + W_OUT;
    __stcs(reinterpret_cast<float4*>(q0 + cA), make_float4(o0[0],o0[1],o0[2],o0[3]));
    __stcs(reinterpret_cast<float4*>(q0 + cB), make_float4(o0[4],o0[5],o0[6],o0[7]));
    __stcs(reinterpret_cast<float4*>(q1 + cA), make_float4(o1[0],o1[1],o1[2],o1[3]));
    __stcs(reinterpret_cast<float4*>(q1 + cB), make_float4(o1[4],o1[5],o1[6],o1[7]));
    __stcs(reinterpret_cast<float4*>(q2 + cA), make_float4(o2[0],o2[1],o2[2],o2[3]));
    __stcs(reinterpret_cast<float4*>(q2 + cB), make_float4(o2[4],o2[5],o2[6],o2[7]));
    __stcs(reinterpret_cast<float4*>(q3 + cA), make_float4(o3[0],o3[1],o3[2],o3[3]));
    __stcs(reinterpret_cast<float4*>(q3 + cB), make_float4(o3[4],o3[5],o3[6],o3[7]));
}

extern "C" void kernel_launch(void* const* d_in, const int* in_sizes, int n_in,
                              void* d_out, int out_size) {
    const float* x = (const float*)d_in[0];   // (8,128,128,128)
    const float* k = (const float*)d_in[1];   // (4,4)
    float* out = (float*)d_out;               // (8,128,256,256)

    // threads = NC * DRP * 32 = 2,097,152 ; blocks = 16384 @ 128 thr
    int threads = 128;
    int blocks = (NC * DRP * 32) / threads;
    Upscale_15358803050749_kernel<<<blocks, threads>>>(x, k, out);
}

// round 9
// speedup vs baseline: 1.0702x; 1.0702x over previous
#include <cuda_runtime.h>
#include <cuda_bf16.h>

// Upscale_15358803050749: upfirdn2d up=2, 4x4 kernel [1,3,3,1]^2, gain 4.
// x: (8,128,128,128) f32 -> out: (8,128,256,256) f32.
//
// Polyphase (reference's dilated conv, pad0=2), separably factored:
//   K[v][u] = C[v]*D[u],  D[u]=K[0][u],  C[v]=K[v][0]/K[0][0]  (C0==1)
//
// R9 = R8 with the duplicated halo-vector (U) global loads replaced by an
// intra-warp smem exchange: thread loads only V (4 LDG.128), stages via
// STS.128 into a per-warp slab, __syncwarp, reads neighbor (lane+1)&31 with
// LDS.128. Lane 31 wraps to lane 0's V = x[0..3] — exactly the values the
// wrapped-output masking already expects (outputs wrap to cols [0..3]).
// Global load instrs halve; L2 read traffic halves.

#define W_IN   128
#define H_IN   128
#define W_OUT  256
#define NC     1024          // 8 * 128 planes
#define DRP    64            // thread-rows per plane (2 input rows each)

__global__ __launch_bounds__(128, 10)
void Upscale_15358803050749_kernel(const float* __restrict__ x,
                                   const float* __restrict__ k,
                                   float* __restrict__ out) {
    __shared__ float4 sm[4 * 4 * 32];     // 4 warps x 4 rows x 32 lanes = 8KB

    int t    = blockIdx.x * blockDim.x + threadIdx.x;
    int lane = t & 31;
    int wid  = (threadIdx.x >> 5) & 3;
    int rp   = t >> 5;
    int ry   = rp & (DRP - 1);
    int pl   = rp >> 6;                   // plane 0..NC-1
    int iy0  = ry * 2;                    // first input row of this thread
    int ix0  = lane * 4;

    const float* xp = x   + pl * (H_IN * W_IN);
    float*       op = out + pl * (256 * W_OUT);

    // ---- 4 independent vector loads (one per row), no halo loads ----
    bool vm = (iy0 > 0);
    bool vc = (iy0 + 2 < H_IN);
    const float* rm_p = xp + (vm ? (iy0 - 1) * W_IN : 0);
    const float* ra_p = xp + iy0 * W_IN;
    const float* rb_p = xp + (iy0 + 1) * W_IN;
    const float* rc_p = xp + (vc ? (iy0 + 2) * W_IN : 0);

    float4 Vm = *reinterpret_cast<const float4*>(rm_p + ix0);
    float4 Va = *reinterpret_cast<const float4*>(ra_p + ix0);
    float4 Vb = *reinterpret_cast<const float4*>(rb_p + ix0);
    float4 Vc = *reinterpret_cast<const float4*>(rc_p + ix0);

    // ---- separable factors (overlaps with load latency) ----
    float D0 = __ldg(k + 0), D1 = __ldg(k + 1), D2 = __ldg(k + 2), D3 = __ldg(k + 3);
    float inv = 1.0f / D0;
    float C1 = __ldg(k + 4)  * inv;
    float C2 = __ldg(k + 8)  * inv;
    float C3 = __ldg(k + 12) * inv;     // C0 == 1

    // ---- intra-warp halo exchange via smem ----
    float4* wsm = sm + wid * 128;
    wsm[0 * 32 + lane] = Vm;
    wsm[1 * 32 + lane] = Va;
    wsm[2 * 32 + lane] = Vb;
    wsm[3 * 32 + lane] = Vc;
    __syncwarp();
    int ln = (lane + 1) & 31;             // lane 31 wraps to lane 0 (= x[0..3])
    float4 Nm = wsm[0 * 32 + ln];
    float4 Na = wsm[1 * 32 + ln];
    float4 Nb = wsm[2 * 32 + ln];
    float4 Nc = wsm[3 * 32 + ln];

    float zm = vm ? 1.f : 0.f;            // row-validity multiplicative mask
    float zc = vc ? 1.f : 0.f;

    // 6 shared source values per row: V.y V.z V.w N.x N.y N.z
    float m6[6] = { Vm.y*zm, Vm.z*zm, Vm.w*zm, Nm.x*zm, Nm.y*zm, Nm.z*zm };
    float a6[6] = { Va.y, Va.z, Va.w, Na.x, Na.y, Na.z };
    float b6[6] = { Vb.y, Vb.z, Vb.w, Nb.x, Nb.y, Nb.z };
    float c6[6] = { Vc.y*zc, Vc.z*zc, Vc.w*zc, Nc.x*zc, Nc.y*zc, Nc.z*zc };

    // ---- vertical combine FIRST (masks commute: per-lane, row-independent)
    float E0[6], O1[6], E2[6], O3[6];
    #pragma unroll
    for (int j = 0; j < 6; j++) {
        E0[j] = C3 * m6[j] + C1 * a6[j];  // out row 2*iy0
        O1[j] = C2 * a6[j] + b6[j];       // out row 2*iy0+1 (C0=1)
        E2[j] = C3 * a6[j] + C1 * b6[j];  // out row 2*iy0+2
        O3[j] = C2 * b6[j] + c6[j];       // out row 2*iy0+3
    }

    bool last = (lane == 31);             // wrap lane: mask x[128] terms

    // ---- horizontal transform per output row: T[6] -> 8 outputs ----
    // T: [0]=x[4l+1] [1]=x[4l+2] [2]=x[4l+3] [3]=x[4l+4] [4]=x[4l+5] [5]=x[4l+6]
    float o0[8], o1[8], o2[8], o3[8];
    #define HOUT(o, T)                                                    \
    {                                                                     \
        float w2z = last ? 0.f : (T)[2];                                  \
        float x3z = last ? 0.f : (T)[3];                                  \
        o[0] = D3*(T)[0] + D1*(T)[1];                                     \
        o[1] = D2*(T)[1] + D0*(T)[2];                                     \
        o[2] = D3*(T)[1] + D1*(T)[2];                                     \
        o[3] = D2*(T)[2] + D0*x3z;                                        \
        o[4] = D3*w2z    + D1*(T)[3];                                     \
        o[5] = D2*(T)[3] + D0*(T)[4];                                     \
        o[6] = D3*(T)[3] + D1*(T)[4];                                     \
        o[7] = D2*(T)[4] + D0*(T)[5];                                     \
    }
    HOUT(o0, E0)
    HOUT(o1, O1)
    HOUT(o2, E2)
    HOUT(o3, O3)
    #undef HOUT

    // ---- stores: two aligned float4 per row; second wraps for lane 31 ----
    int cA = 8 * lane + 4;                 // cols [8l+4..8l+7]
    int cB = (8 * lane + 8) & (W_OUT - 1); // cols [8l+8..8l+11] (lane31 -> 0..3)
    float* q0 = op + (2 * iy0) * W_OUT;
    float* q1 = q0 + W_OUT;
    float* q2 = q1 + W_OUT;
    float* q3 = q2 + W_OUT;
    __stcs(reinterpret_cast<float4*>(q0 + cA), make_float4(o0[0],o0[1],o0[2],o0[3]));
    __stcs(reinterpret_cast<float4*>(q0 + cB), make_float4(o0[4],o0[5],o0[6],o0[7]));
    __stcs(reinterpret_cast<float4*>(q1 + cA), make_float4(o1[0],o1[1],o1[2],o1[3]));
    __stcs(reinterpret_cast<float4*>(q1 + cB), make_float4(o1[4],o1[5],o1[6],o1[7]));
    __stcs(reinterpret_cast<float4*>(q2 + cA), make_float4(o2[0],o2[1],o2[2],o2[3]));
    __stcs(reinterpret_cast<float4*>(q2 + cB), make_float4(o2[4],o2[5],o2[6],o2[7]));
    __stcs(reinterpret_cast<float4*>(q3 + cA), make_float4(o3[0],o3[1],o3[2],o3[3]));
    __stcs(reinterpret_cast<float4*>(q3 + cB), make_float4(o3[4],o3[5],o3[6],o3[7]));
}

extern "C" void kernel_launch(void* const* d_in, const int* in_sizes, int n_in,
                              void* d_out, int out_size) {
    const float* x = (const float*)d_in[0];   // (8,128,128,128)
    const float* k = (const float*)d_in[1];   // (4,4)
    float* out = (float*)d_out;               // (8,128,256,256)

    // threads = NC * DRP * 32 = 2,097,152 ; blocks = 16384 @ 128 thr
    int threads = 128;
    int blocks = (NC * DRP * 32) / threads;
    Upscale_15358803050749_kernel<<<blocks, threads>>>(x, k, out);
}